// round 10
// baseline (speedup 1.0000x reference)
#include <cuda_runtime.h>
#include <math.h>
#include <float.h>
#include <stdint.h>

#define TT   80
#define DIN  4096
#define HH   512
#define HD2  1024
#define GE   2048      /* 4*HH  */
#define VV   32000
#define KB   4
#define ML   20
#define NBC  132       /* blocks for logits kernel */

// ---------------- device scratch ----------------
__device__ float g_Xpre[TT*GE];            // x@Wih_f.T (NO bias)
__device__ float g_Gb[GE];                 // video[79]@Wih_b.T + b_b
__device__ float g_encH[2][HH];
__device__ float g_encC[HH];
__device__ float g_h[KB*HD2], g_c[KB*HD2], g_h2[KB*HD2], g_c2[KB*HD2];
__device__ float g_o[KB*HD2];
__device__ float g_logits[KB*VV];
__device__ float g_sc[KB*VV];
__device__ int   g_tok[2][KB*(ML+1)];
__device__ float g_bp[KB];

// ---------------- correctly-rounded activations (immune to fast-math) ----------------
__device__ __forceinline__ float sigm32(float x){
    return (float)(1.0/(1.0 + exp(-(double)x)));
}
__device__ __forceinline__ float tanh32(float x){
    return (float)tanh((double)x);
}
__device__ __forceinline__ float exp32(float x){
    return (float)exp((double)x);
}
__device__ __forceinline__ float dot4(float4 a, float4 b){
    return a.x*b.x + a.y*b.y + a.z*b.z + a.w*b.w;
}
// FTZ: XLA fp32 flushes subnormal results to zero
__device__ __forceinline__ float ftz(float x){
    return (fabsf(x) < FLT_MIN) ? 0.f : x;
}

// lax.top_k ordering: larger value first; ties -> smaller flat index first
__device__ __forceinline__ bool bet(float v1,int i1,float v2,int i2){
    return (v1 > v2) || (v1 == v2 && i1 < i2);
}
__device__ __forceinline__ void ins4(float v,int i,float tv[4],int ti[4]){
    if (bet(v,i,tv[3],ti[3])){
        tv[3]=v; ti[3]=i;
        if (bet(tv[3],ti[3],tv[2],ti[2])){ float a=tv[2];int b=ti[2]; tv[2]=tv[3];ti[2]=ti[3]; tv[3]=a;ti[3]=b; }
        if (bet(tv[2],ti[2],tv[1],ti[1])){ float a=tv[1];int b=ti[1]; tv[1]=tv[2];ti[1]=ti[2]; tv[2]=a;ti[2]=b; }
        if (bet(tv[1],ti[1],tv[0],ti[0])){ float a=tv[0];int b=ti[0]; tv[0]=tv[1];ti[0]=ti[1]; tv[1]=a;ti[1]=b; }
    }
}

// ============ init ============
__global__ void k_init(){
    int g = threadIdx.x;
    if (g < KB*(ML+1)) g_tok[0][g] = 1;                 // BOS
    if (g < KB) g_bp[g] = (g==0) ? 1.f : 0.f;
    if (g < HH) { g_encH[0][g] = 0.f; g_encC[g] = 0.f; }
    for (int i = g; i < KB*HD2; i += 512) g_c[i] = 0.f;
}

// ============ Xpre = video @ Wih_f.T  (no bias) ============
__global__ void __launch_bounds__(256) k_xpre(const float* __restrict__ video,
                                              const float* __restrict__ W)
{
    const int wid = threadIdx.x>>5, lane = threadIdx.x&31;
    const int j = blockIdx.x*8 + wid;                  // 0..2047
    const float4* wr = (const float4*)(W + (size_t)j*DIN);
    for (int t0 = 0; t0 < TT; t0 += 16){
        float acc[16];
        #pragma unroll
        for (int u=0;u<16;u++) acc[u]=0.f;
        for (int c = 0; c < 8; c++){
            float4 w[4];
            #pragma unroll
            for (int q=0;q<4;q++) w[q] = wr[c*128 + lane + 32*q];
            #pragma unroll
            for (int u=0;u<16;u++){
                const float4* xr = (const float4*)(video + (size_t)(t0+u)*DIN);
                float a = 0.f;
                #pragma unroll
                for (int q=0;q<4;q++) a += dot4(w[q], xr[c*128 + lane + 32*q]);
                acc[u] += a;
            }
        }
        #pragma unroll
        for (int off=16; off; off>>=1)
            #pragma unroll
            for (int u=0;u<16;u++) acc[u] += __shfl_xor_sync(0xffffffffu, acc[u], off);
        if (lane == 0)
            #pragma unroll
            for (int u=0;u<16;u++) g_Xpre[(size_t)(t0+u)*GE + j] = acc[u];
    }
}

// ============ Gb = video[79] @ Wih_b.T + b_b ============
__global__ void __launch_bounds__(256) k_gb(const float* __restrict__ video,
                                            const float* __restrict__ W,
                                            const float* __restrict__ b)
{
    const int wid = threadIdx.x>>5, lane = threadIdx.x&31;
    const int r = blockIdx.x*8 + wid;                  // 0..2047
    const float4* wr = (const float4*)(W + (size_t)r*DIN);
    const float4* x4 = (const float4*)(video + (size_t)(TT-1)*DIN);
    float a = 0.f;
    #pragma unroll 8
    for (int q = 0; q < 32; q++)
        a += dot4(wr[lane+32*q], x4[lane+32*q]);
    #pragma unroll
    for (int off=16; off; off>>=1) a += __shfl_xor_sync(0xffffffffu, a, off);
    if (lane == 0) g_Gb[r] = __fadd_rn(a, b[r]);
}

// ============ one encoder recurrence step ============
__global__ void __launch_bounds__(256) k_enc(const float* __restrict__ Whh,
                                             const float* __restrict__ b, int t)
{
    __shared__ float sh[HH];
    const int tid = threadIdx.x, wid = tid>>5, lane = tid&31;
    const float* hin = g_encH[t&1];
    for (int i = tid; i < HH; i += 256) sh[i] = hin[i];
    __syncthreads();
    const int j = blockIdx.x*8 + wid;                  // 0..511
    const float4* h4 = (const float4*)sh;
    float acc[4];
    #pragma unroll
    for (int g = 0; g < 4; g++){
        const float4* w4 = (const float4*)(Whh + (size_t)(g*HH + j)*HH);
        float a = 0.f;
        #pragma unroll
        for (int q = 0; q < 4; q++) a += dot4(w4[lane+32*q], h4[lane+32*q]);
        acc[g] = a;
    }
    #pragma unroll
    for (int off=16; off; off>>=1)
        #pragma unroll
        for (int g = 0; g < 4; g++) acc[g] += __shfl_xor_sync(0xffffffffu, acc[g], off);
    if (lane == 0){
        float gi = __fadd_rn(__fadd_rn(g_Xpre[(size_t)t*GE + j],        acc[0]), b[j]);
        float gf = __fadd_rn(__fadd_rn(g_Xpre[(size_t)t*GE + HH + j],   acc[1]), b[HH+j]);
        float gg = __fadd_rn(__fadd_rn(g_Xpre[(size_t)t*GE + 2*HH + j], acc[2]), b[2*HH+j]);
        float go = __fadd_rn(__fadd_rn(g_Xpre[(size_t)t*GE + 3*HH + j], acc[3]), b[3*HH+j]);
        float c2 = __fadd_rn(__fmul_rn(sigm32(gf), g_encC[j]),
                             __fmul_rn(sigm32(gi), tanh32(gg)));
        float h2 = __fmul_rn(sigm32(go), tanh32(c2));
        g_encC[j] = c2;
        g_encH[(t+1)&1][j] = h2;
    }
}

// ============ decoder init: h0 = [hf, hb] broadcast ============
__global__ void k_decinit(){
    int g = threadIdx.x;
    if (g < HH){
        float hf = g_encH[0][g];                       // TT even -> buf 0
        float gi = g_Gb[g];
        float gg = g_Gb[2*HH+g];
        float go = g_Gb[3*HH+g];
        float cb = __fmul_rn(sigm32(gi), tanh32(gg));  // c0=0 -> forget term is +0
        float hb = __fmul_rn(sigm32(go), tanh32(cb));
        #pragma unroll
        for (int k = 0; k < KB; k++){
            g_h[k*HD2 + g]      = hf;
            g_h[k*HD2 + HH + g] = hb;
        }
    }
}

// ============ decode A: LSTM cell for 4 beams ============
__global__ void __launch_bounds__(256) k_decA(const float* __restrict__ emb,
                                              const float* __restrict__ dWih,
                                              const float* __restrict__ dWhh,
                                              const float* __restrict__ db,
                                              int t)
{
    __shared__ float xs[KB*HD2];
    __shared__ float hs[KB*HD2];
    const int tid = threadIdx.x, wid = tid>>5, lane = tid&31;
    const int cur = t & 1;
    for (int i = tid; i < KB*HD2; i += 256){
        int k = i>>10, j = i&1023;
        int tk = g_tok[cur][k*(ML+1)+t];
        xs[i] = emb[(size_t)tk*HD2 + j];
        hs[i] = g_h[i];
    }
    __syncthreads();
    const int j = blockIdx.x*8 + wid;                  // 0..1023
    const float4* x4 = (const float4*)xs;
    const float4* h4 = (const float4*)hs;
    float aA[4][KB], aB[4][KB];
    #pragma unroll
    for (int g=0;g<4;g++)
        #pragma unroll
        for (int k=0;k<KB;k++){ aA[g][k]=0.f; aB[g][k]=0.f; }
    #pragma unroll 2
    for (int q = 0; q < 8; q++){
        int m = lane + 32*q;
        #pragma unroll
        for (int g = 0; g < 4; g++){
            float4 wi = __ldg((const float4*)(dWih + (size_t)(g*HD2+j)*HD2) + m);
            float4 wh = __ldg((const float4*)(dWhh + (size_t)(g*HD2+j)*HD2) + m);
            #pragma unroll
            for (int k = 0; k < KB; k++){
                aA[g][k] += dot4(wi, x4[k*256+m]);
                aB[g][k] += dot4(wh, h4[k*256+m]);
            }
        }
    }
    #pragma unroll
    for (int off=16; off; off>>=1)
        #pragma unroll
        for (int g=0;g<4;g++)
            #pragma unroll
            for (int k=0;k<KB;k++){
                aA[g][k] += __shfl_xor_sync(0xffffffffu, aA[g][k], off);
                aB[g][k] += __shfl_xor_sync(0xffffffffu, aB[g][k], off);
            }
    if (lane == 0){
        float b0 = db[j], b1 = db[HD2+j], b2 = db[2*HD2+j], b3 = db[3*HD2+j];
        #pragma unroll
        for (int k = 0; k < KB; k++){
            float gi = __fadd_rn(__fadd_rn(aA[0][k], aB[0][k]), b0);
            float gf = __fadd_rn(__fadd_rn(aA[1][k], aB[1][k]), b1);
            float gg = __fadd_rn(__fadd_rn(aA[2][k], aB[2][k]), b2);
            float go = __fadd_rn(__fadd_rn(aA[3][k], aB[3][k]), b3);
            float c2 = __fadd_rn(__fmul_rn(sigm32(gf), g_c[k*HD2+j]),
                                 __fmul_rn(sigm32(gi), tanh32(gg)));
            float h2 = __fmul_rn(sigm32(go), tanh32(c2));
            g_c2[k*HD2+j] = c2;
            g_h2[k*HD2+j] = h2;
        }
    }
}

// ============ decode B: o = tanh(W_cat @ [h2, x] + b_cat) ============
__global__ void __launch_bounds__(256) k_decB(const float* __restrict__ emb,
                                              const float* __restrict__ Wcat,
                                              const float* __restrict__ bcat,
                                              int t)
{
    __shared__ float xs[KB*HD2];
    __shared__ float hs[KB*HD2];
    const int tid = threadIdx.x, wid = tid>>5, lane = tid&31;
    const int cur = t & 1;
    for (int i = tid; i < KB*HD2; i += 256){
        int k = i>>10, j = i&1023;
        int tk = g_tok[cur][k*(ML+1)+t];
        xs[i] = emb[(size_t)tk*HD2 + j];
        hs[i] = g_h2[i];
    }
    __syncthreads();
    const int j = blockIdx.x*8 + wid;                  // 0..1023
    const float4* x4 = (const float4*)xs;
    const float4* h4 = (const float4*)hs;
    float aH[KB] = {0.f,0.f,0.f,0.f};
    float aX[KB] = {0.f,0.f,0.f,0.f};
    const float4* wr = (const float4*)(Wcat + (size_t)j*(2*HD2));
    #pragma unroll 2
    for (int q = 0; q < 8; q++){
        int m = lane + 32*q;
        float4 w1 = __ldg(&wr[m]);
        float4 w2 = __ldg(&wr[256+m]);
        #pragma unroll
        for (int k = 0; k < KB; k++){
            aH[k] += dot4(w1, h4[k*256+m]);
            aX[k] += dot4(w2, x4[k*256+m]);
        }
    }
    #pragma unroll
    for (int off=16; off; off>>=1)
        #pragma unroll
        for (int k=0;k<KB;k++){
            aH[k] += __shfl_xor_sync(0xffffffffu, aH[k], off);
            aX[k] += __shfl_xor_sync(0xffffffffu, aX[k], off);
        }
    if (lane == 0){
        float bb = bcat[j];
        #pragma unroll
        for (int k = 0; k < KB; k++)
            g_o[k*HD2+j] = tanh32(__fadd_rn(__fadd_rn(aH[k], aX[k]), bb));
    }
}

// ============ decode C: raw logits ============
__global__ void __launch_bounds__(256) k_decC(const float* __restrict__ Wout,
                                              const float* __restrict__ bout)
{
    __shared__ float os[KB*HD2];
    const int tid = threadIdx.x, wid = tid>>5, lane = tid&31;
    const int bid = blockIdx.x;
    for (int i = tid; i < KB*HD2; i += 256) os[i] = g_o[i];
    __syncthreads();
    const float4* o4 = (const float4*)os;
    for (int v = bid*8 + wid; v < VV; v += NBC*8){
        float acc[KB] = {0.f,0.f,0.f,0.f};
        const float4* w4 = (const float4*)(Wout + (size_t)v*HD2);
        #pragma unroll
        for (int q = 0; q < 8; q++){
            int m = lane + 32*q;
            float4 w = __ldg(&w4[m]);
            #pragma unroll
            for (int k = 0; k < KB; k++)
                acc[k] += dot4(w, o4[k*256+m]);
        }
        #pragma unroll
        for (int off=16; off; off>>=1)
            #pragma unroll
            for (int k=0;k<KB;k++)
                acc[k] += __shfl_xor_sync(0xffffffffu, acc[k], off);
        if (lane == 0){
            float bo = __ldg(&bout[v]);
            #pragma unroll
            for (int k = 0; k < KB; k++)
                g_logits[(size_t)k*VV + v] = __fadd_rn(acc[k], bo);
        }
    }
}

// ============ decode S: sc = bp * softmax(logits), fp32 with FTZ (XLA semantics) ============
__global__ void __launch_bounds__(1024) k_soft()
{
    __shared__ float red[1024];
    const int k = blockIdx.x, tid = threadIdx.x;
    const float* L = g_logits + (size_t)k*VV;
    // exact per-beam max
    float m = -FLT_MAX;
    for (int v = tid; v < VV; v += 1024) m = fmaxf(m, L[v]);
    red[tid] = m; __syncthreads();
    for (int s = 512; s; s >>= 1){
        if (tid < s) red[tid] = fmaxf(red[tid], red[tid+s]);
        __syncthreads();
    }
    m = red[0]; __syncthreads();
    // fp32 sum of exp, flushing subnormal exps (FTZ)
    float s_ = 0.f;
    for (int v = tid; v < VV; v += 1024)
        s_ = __fadd_rn(s_, ftz(exp32(__fsub_rn(L[v], m))));
    red[tid] = s_; __syncthreads();
    for (int s = 512; s; s >>= 1){
        if (tid < s) red[tid] = __fadd_rn(red[tid], red[tid+s]);
        __syncthreads();
    }
    const float S = red[0];
    const float bk = g_bp[k];
    for (int v = tid; v < VV; v += 1024){
        float e  = ftz(exp32(__fsub_rn(L[v], m)));     // FTZ exp
        float pf = ftz(__fdiv_rn(e, S));               // FTZ probs
        float sc = ftz(__fmul_rn(bk, pf));             // FTZ score -> exact 0 below FLT_MIN
        g_sc[(size_t)k*VV + v] = sc;
    }
}

// ============ decode T: literal global top-4 over g_sc + beam update ============
__global__ void __launch_bounds__(1024) k_sel(int t, float* __restrict__ out, int out_size)
{
    __shared__ float cv[4096]; __shared__ int ci[4096];
    __shared__ int   s_bi[KB], s_nt[KB];
    __shared__ float s_val[KB];
    const int tid = threadIdx.x;
    const int cur = t & 1, nxt = (t+1) & 1;
    const int CH = (KB*VV)/1024;                       // 125, exact

    float tv[4] = {-FLT_MAX,-FLT_MAX,-FLT_MAX,-FLT_MAX};
    int   ti[4] = {0x7fffffff,0x7fffffff,0x7fffffff,0x7fffffff};
    const int lo = tid*CH;
    for (int i = lo; i < lo+CH; i++) ins4(g_sc[i], i, tv, ti);
    #pragma unroll
    for (int j = 0; j < 4; j++){ cv[tid*4+j] = tv[j]; ci[tid*4+j] = ti[j]; }
    __syncthreads();
    if (tid == 0){
        float fv[4] = {-FLT_MAX,-FLT_MAX,-FLT_MAX,-FLT_MAX};
        int   fi[4] = {0x7fffffff,0x7fffffff,0x7fffffff,0x7fffffff};
        for (int i = 0; i < 4096; i++) ins4(cv[i], ci[i], fv, fi);
        #pragma unroll
        for (int j = 0; j < 4; j++){
            s_bi[j]  = fi[j] / VV;
            s_nt[j]  = fi[j] - (fi[j]/VV)*VV;
            s_val[j] = fv[j];
        }
    }
    __syncthreads();
    if (tid < KB) g_bp[tid] = s_val[tid];
    if (tid < KB*(ML+1)){
        int kk = tid/(ML+1), col = tid%(ML+1);
        int val = (col == t+1) ? s_nt[kk] : g_tok[cur][s_bi[kk]*(ML+1)+col];
        g_tok[nxt][tid] = val;
        if (t == ML-1) out[tid] = (float)val;
    }
    if (t == ML-1 && out_size >= KB*(ML+1)+KB && tid < KB)
        out[KB*(ML+1)+tid] = s_val[tid];
    for (int i = tid; i < KB*HD2; i += 1024){
        int kk = i>>10, j = i&1023;
        g_h[i] = g_h2[(size_t)s_bi[kk]*HD2 + j];
        g_c[i] = g_c2[(size_t)s_bi[kk]*HD2 + j];
    }
}

// ---------------- host ----------------
static int pick_idx(const int* sz, int n, int want, int occ){
    int c = 0;
    for (int i = 0; i < n; i++)
        if (sz[i] == want){ if (c == occ) return i; c++; }
    return -1;
}

extern "C" void kernel_launch(void* const* d_in, const int* in_sizes, int n_in,
                              void* d_out, int out_size)
{
    int iv   = pick_idx(in_sizes, n_in, TT*DIN, 0);
    int ie   = pick_idx(in_sizes, n_in, VV*HD2, 0);
    int iWf  = pick_idx(in_sizes, n_in, GE*DIN, 0);
    int iHf  = pick_idx(in_sizes, n_in, GE*HH, 0);
    int ibf  = pick_idx(in_sizes, n_in, GE, 0);
    int iWb  = pick_idx(in_sizes, n_in, GE*DIN, 1);
    int ibb  = pick_idx(in_sizes, n_in, GE, 1);
    int idW  = pick_idx(in_sizes, n_in, 4*HD2*HD2, 0);
    int idH  = pick_idx(in_sizes, n_in, 4*HD2*HD2, 1);
    int idb  = pick_idx(in_sizes, n_in, 4*HD2, 0);
    int iWc  = pick_idx(in_sizes, n_in, HD2*2*HD2, 0);
    int ibc  = pick_idx(in_sizes, n_in, HD2, 0);
    int iWo  = pick_idx(in_sizes, n_in, VV*HD2, 1);
    int ibo  = pick_idx(in_sizes, n_in, VV, 0);
    if (iv<0||ie<0||iWf<0||iHf<0||ibf<0||iWb<0||ibb<0||idW<0||idH<0||idb<0||iWc<0||ibc<0||iWo<0||ibo<0){
        iv=0; ie=1; iWf=2; iHf=3; ibf=4; iWb=5; ibb=7; idW=8; idH=9; idb=10; iWc=11; ibc=12; iWo=13; ibo=14;
    }
    const float* video = (const float*)d_in[iv];
    const float* emb   = (const float*)d_in[ie];
    const float* Wih_f = (const float*)d_in[iWf];
    const float* Whh_f = (const float*)d_in[iHf];
    const float* b_f   = (const float*)d_in[ibf];
    const float* Wih_b = (const float*)d_in[iWb];
    const float* b_b   = (const float*)d_in[ibb];
    const float* dWih  = (const float*)d_in[idW];
    const float* dWhh  = (const float*)d_in[idH];
    const float* db    = (const float*)d_in[idb];
    const float* Wcat  = (const float*)d_in[iWc];
    const float* bcat  = (const float*)d_in[ibc];
    const float* Wout  = (const float*)d_in[iWo];
    const float* bout  = (const float*)d_in[ibo];
    float* out = (float*)d_out;

    k_init<<<1, 512>>>();
    k_xpre<<<256, 256>>>(video, Wih_f);
    k_gb<<<256, 256>>>(video, Wih_b, b_b);
    for (int t = 0; t < TT; t++)
        k_enc<<<64, 256>>>(Whh_f, b_f, t);
    k_decinit<<<1, 512>>>();
    for (int t = 0; t < ML; t++){
        k_decA<<<128, 256>>>(emb, dWih, dWhh, db, t);
        k_decB<<<128, 256>>>(emb, Wcat, bcat, t);
        k_decC<<<NBC, 256>>>(Wout, bout);
        k_soft<<<KB, 1024>>>();
        k_sel<<<1, 1024>>>(t, out, out_size);
    }
}

// round 11
// speedup vs baseline: 4.8208x; 4.8208x over previous
#include <cuda_runtime.h>
#include <math.h>
#include <float.h>
#include <stdint.h>

#define TT   80
#define DIN  4096
#define HH   512
#define HD2  1024
#define GE   2048      /* 4*HH  */
#define VV   32000
#define KB   4
#define ML   20
#define NB   132
#define NT   256
#define NWARP (NB*8)   /* 1056 */

// ---------------- device scratch ----------------
__device__ float g_Xpre[TT*GE];            // video @ Wih_f.T + b_f
__device__ float g_Gb[GE];                 // video[79] @ Wih_b.T + b_b
__device__ float g_encH[2][HH];
__device__ float g_encC[HH];
__device__ float g_h[KB*HD2], g_c[KB*HD2], g_h2[KB*HD2], g_c2[KB*HD2];
__device__ float g_o[KB*HD2];
__device__ float g_logits[KB*VV];
__device__ int   g_tok[2][KB*(ML+1)];
__device__ float g_bp[KB];
__device__ float g_pmax[NB*KB];
__device__ float g_psum[NB*KB];
__device__ float g_candv[NB*KB];
__device__ int   g_candi[NB*KB];
__device__ unsigned g_cnt = 0;
__device__ volatile unsigned g_epoch = 0;

// ---------------- helpers ----------------
__device__ __forceinline__ float sigm(float x){ return 1.f/(1.f+expf(-x)); }
__device__ __forceinline__ float dot4(float4 a, float4 b){
    return a.x*b.x + a.y*b.y + a.z*b.z + a.w*b.w;
}
// FTZ: XLA fp32 flushes subnormal results to zero (THE critical semantic)
__device__ __forceinline__ float ftz(float x){
    return (fabsf(x) < FLT_MIN) ? 0.f : x;
}

// lax.top_k ordering: larger value first; ties -> smaller flat index first
__device__ __forceinline__ bool bet(float v1,int i1,float v2,int i2){
    return (v1 > v2) || (v1 == v2 && i1 < i2);
}
__device__ __forceinline__ void ins4(float v,int i,float tv[4],int ti[4]){
    if (bet(v,i,tv[3],ti[3])){
        tv[3]=v; ti[3]=i;
        if (bet(tv[3],ti[3],tv[2],ti[2])){ float a=tv[2];int b=ti[2]; tv[2]=tv[3];ti[2]=ti[3]; tv[3]=a;ti[3]=b; }
        if (bet(tv[2],ti[2],tv[1],ti[1])){ float a=tv[1];int b=ti[1]; tv[1]=tv[2];ti[1]=ti[2]; tv[2]=a;ti[2]=b; }
        if (bet(tv[1],ti[1],tv[0],ti[0])){ float a=tv[0];int b=ti[0]; tv[0]=tv[1];ti[0]=ti[1]; tv[1]=a;ti[1]=b; }
    }
}
__device__ __forceinline__ void warp_merge4(float tv[4],int ti[4]){
    #pragma unroll
    for (int off=16; off; off>>=1){
        float ov[4]; int oi[4];
        #pragma unroll
        for (int j=0;j<4;j++){
            ov[j]=__shfl_xor_sync(0xffffffffu,tv[j],off);
            oi[j]=__shfl_xor_sync(0xffffffffu,ti[j],off);
        }
        #pragma unroll
        for (int j=0;j<4;j++) ins4(ov[j],oi[j],tv,ti);
    }
}

// grid-wide barrier, release/acquire correct (replay-safe: counter self-resets,
// epoch monotonic across graph replays)
__device__ __forceinline__ void gbar(){
    __threadfence();            // release: my stores visible at L2
    __syncthreads();
    if (threadIdx.x == 0){
        unsigned e = g_epoch;
        if (atomicAdd(&g_cnt, 1u) == NB-1u){
            g_cnt = 0;
            __threadfence();
            g_epoch = e + 1u;
        } else {
            while (g_epoch == e) { __nanosleep(64); }
        }
    }
    __syncthreads();
    __threadfence();            // acquire
}

__global__ void __launch_bounds__(NT, 1) beam_kernel(
    const float* __restrict__ video, const float* __restrict__ emb,
    const float* __restrict__ Wih_f, const float* __restrict__ Whh_f, const float* __restrict__ b_f,
    const float* __restrict__ Wih_b, const float* __restrict__ b_b,
    const float* __restrict__ dWih, const float* __restrict__ dWhh, const float* __restrict__ db,
    const float* __restrict__ Wcat, const float* __restrict__ bcat,
    const float* __restrict__ Wout, const float* __restrict__ bout,
    float* __restrict__ out, int out_size)
{
    __shared__ float4 smem4[2048];           // 32 KB general staging
    float* smem = (float*)smem4;
    __shared__ float sred[8*KB];
    __shared__ float scv[8*KB];  __shared__ int sci[8*KB];
    __shared__ int   s_bi[KB], s_nt[KB];
    __shared__ float s_gmax[KB], s_S[KB], s_bpold[KB];

    const int bid = blockIdx.x, tid = threadIdx.x;
    const int wid = tid>>5, lane = tid&31;
    const int gwarp = bid*8 + wid;

    // =============== P0: init + encoder input projections ===============
    {
        int g = bid*NT + tid;
        if (g < KB*(ML+1)) g_tok[0][g] = 1;                 // BOS
        if (g < KB) g_bp[g] = (g==0) ? 1.f : 0.f;
        if (g < HH) { g_encH[0][g] = 0.f; g_encC[g] = 0.f; }
        for (int i = g; i < KB*HD2; i += NB*NT) g_c[i] = 0.f;
    }

    for (int job = bid; job < 168; job += NB){
        if (job < 160){
            // fwd GEMM tile: 16 t-rows x 64 j-cols over K=4096 (bias folded in)
            const int t0 = (job>>5)*16, j0 = (job&31)*64;
            float* Xs = smem;                // [16][65]
            float* Ws = smem + 16*65;        // [64][65]
            const int jj = tid & 63, tr = tid >> 6;
            float acc[4] = {0.f,0.f,0.f,0.f};
            for (int kc = 0; kc < DIN; kc += 64){
                __syncthreads();
                for (int i = tid; i < 16*64; i += NT){
                    int r = i>>6, kk = i&63;
                    Xs[r*65+kk] = __ldg(&video[(size_t)(t0+r)*DIN + kc+kk]);
                }
                for (int i = tid; i < 64*64; i += NT){
                    int r = i>>6, kk = i&63;
                    Ws[r*65+kk] = __ldg(&Wih_f[(size_t)(j0+r)*DIN + kc+kk]);
                }
                __syncthreads();
                #pragma unroll 8
                for (int kk = 0; kk < 64; kk++){
                    float w = Ws[jj*65+kk];
                    #pragma unroll
                    for (int u = 0; u < 4; u++)
                        acc[u] += Xs[(tr+4*u)*65+kk]*w;
                }
            }
            float bb = __ldg(&b_f[j0+jj]);
            #pragma unroll
            for (int u = 0; u < 4; u++)
                g_Xpre[(size_t)(t0+tr+4*u)*GE + j0+jj] = acc[u] + bb;
            __syncthreads();
        } else {
            // Gb = video[79] @ Wih_b.T + b_b
            const int r0 = (job-160)*256 + wid*32;
            const float4* x4 = (const float4*)(video + (size_t)(TT-1)*DIN);
            for (int rr = 0; rr < 32; rr++){
                int row = r0 + rr;
                const float4* w4 = (const float4*)(Wih_b + (size_t)row*DIN);
                float a = 0.f;
                #pragma unroll 8
                for (int q = 0; q < 32; q++)
                    a += dot4(__ldg(&w4[lane+32*q]), __ldg(&x4[lane+32*q]));
                #pragma unroll
                for (int o = 16; o; o >>= 1) a += __shfl_xor_sync(0xffffffffu,a,o);
                if (lane == 0) g_Gb[row] = a + __ldg(&b_b[row]);
            }
        }
    }
    gbar();

    // =============== P1: forward encoder recurrence (80 steps) ===============
    for (int t = 0; t < TT; t++){
        const float* hin = g_encH[t&1];
        for (int i = tid; i < HH; i += NT) smem[i] = __ldcg(&hin[i]);
        __syncthreads();
        if (gwarp < HH){
            const int j = gwarp;
            const float4* h4 = (const float4*)smem;
            float acc[4];
            #pragma unroll
            for (int g = 0; g < 4; g++){
                const float4* w4 = (const float4*)(Whh_f + (size_t)(g*HH + j)*HH);
                float a = 0.f;
                #pragma unroll
                for (int q = 0; q < 4; q++)
                    a += dot4(__ldg(&w4[lane+32*q]), h4[lane+32*q]);
                acc[g] = a;
            }
            #pragma unroll
            for (int o = 16; o; o >>= 1)
                #pragma unroll
                for (int g = 0; g < 4; g++)
                    acc[g] += __shfl_xor_sync(0xffffffffu, acc[g], o);
            if (lane == 0){
                float gi = acc[0] + __ldcg(&g_Xpre[(size_t)t*GE + j]);
                float gf = acc[1] + __ldcg(&g_Xpre[(size_t)t*GE + HH + j]);
                float gg = acc[2] + __ldcg(&g_Xpre[(size_t)t*GE + 2*HH + j]);
                float go = acc[3] + __ldcg(&g_Xpre[(size_t)t*GE + 3*HH + j]);
                float c2 = sigm(gf)*__ldcg(&g_encC[j]) + sigm(gi)*tanhf(gg);
                float h2 = sigm(go)*tanhf(c2);
                g_encC[j] = c2;
                g_encH[(t+1)&1][j] = h2;
            }
        }
        gbar();
    }

    // =============== P2: decoder init (h0 = [hf, hb] broadcast) ===============
    {
        int g = bid*NT + tid;
        if (g < HH){
            float hf = __ldcg(&g_encH[0][g]);   // TT even -> buf 0
            float gi = __ldcg(&g_Gb[g]);
            float gg = __ldcg(&g_Gb[2*HH+g]);
            float go = __ldcg(&g_Gb[3*HH+g]);
            float cb = sigm(gi)*tanhf(gg);      // c0=0 -> forget term vanishes
            float hb = sigm(go)*tanhf(cb);
            #pragma unroll
            for (int k = 0; k < KB; k++){
                g_h[k*HD2 + g]      = hf;
                g_h[k*HD2 + HH + g] = hb;
            }
        }
    }
    gbar();

    // =============== P3: decoder beam search (20 steps) ===============
    float4* xs = smem4;            // [4][256] f4 = x (4x1024 f32)
    float4* hs = smem4 + 4*256;    // [4][256] f4 = h / h2

    for (int t = 0; t < ML; t++){
        const int cur = t & 1;

        // -------- A: decoder LSTM cell --------
        for (int i = tid; i < KB*HD2; i += NT){
            int k = i>>10, j = i&1023;
            int tk = __ldcg(&g_tok[cur][k*(ML+1)+t]);
            ((float*)xs)[i] = __ldg(&emb[(size_t)tk*HD2 + j]);
            ((float*)hs)[i] = __ldcg(&g_h[i]);
        }
        __syncthreads();
        for (int j = gwarp; j < HD2; j += NWARP){
            float acc[4][KB];
            #pragma unroll
            for (int g = 0; g < 4; g++)
                #pragma unroll
                for (int k = 0; k < KB; k++) acc[g][k] = 0.f;
            #pragma unroll 2
            for (int q = 0; q < 8; q++){
                int m = lane + 32*q;
                #pragma unroll
                for (int g = 0; g < 4; g++){
                    float4 wi = __ldg((const float4*)(dWih + (size_t)(g*HD2+j)*HD2) + m);
                    float4 wh = __ldg((const float4*)(dWhh + (size_t)(g*HD2+j)*HD2) + m);
                    #pragma unroll
                    for (int k = 0; k < KB; k++)
                        acc[g][k] += dot4(wi, xs[k*256+m]) + dot4(wh, hs[k*256+m]);
                }
            }
            #pragma unroll
            for (int o = 16; o; o >>= 1)
                #pragma unroll
                for (int g = 0; g < 4; g++)
                    #pragma unroll
                    for (int k = 0; k < KB; k++)
                        acc[g][k] += __shfl_xor_sync(0xffffffffu, acc[g][k], o);
            if (lane == 0){
                float bi_ = __ldg(&db[j]),       bf_ = __ldg(&db[HD2+j]);
                float bg_ = __ldg(&db[2*HD2+j]), bo_ = __ldg(&db[3*HD2+j]);
                #pragma unroll
                for (int k = 0; k < KB; k++){
                    float gi = acc[0][k]+bi_, gf = acc[1][k]+bf_;
                    float gg = acc[2][k]+bg_, go = acc[3][k]+bo_;
                    float c2 = sigm(gf)*__ldcg(&g_c[k*HD2+j]) + sigm(gi)*tanhf(gg);
                    float h2 = sigm(go)*tanhf(c2);
                    g_c2[k*HD2+j] = c2;
                    g_h2[k*HD2+j] = h2;
                }
            }
        }
        gbar();

        // -------- B: o = tanh(W_cat @ [h2, x] + b_cat) --------
        for (int i = tid; i < KB*HD2; i += NT) ((float*)hs)[i] = __ldcg(&g_h2[i]);
        __syncthreads();
        for (int j = gwarp; j < HD2; j += NWARP){
            float acc[KB] = {0.f,0.f,0.f,0.f};
            const float4* wr = (const float4*)(Wcat + (size_t)j*(2*HD2));
            #pragma unroll 2
            for (int q = 0; q < 8; q++){
                int m = lane + 32*q;
                float4 w1 = __ldg(&wr[m]);
                float4 w2 = __ldg(&wr[256+m]);
                #pragma unroll
                for (int k = 0; k < KB; k++)
                    acc[k] += dot4(w1, hs[k*256+m]) + dot4(w2, xs[k*256+m]);
            }
            #pragma unroll
            for (int o = 16; o; o >>= 1)
                #pragma unroll
                for (int k = 0; k < KB; k++)
                    acc[k] += __shfl_xor_sync(0xffffffffu, acc[k], o);
            if (lane == 0){
                float bb = __ldg(&bcat[j]);
                #pragma unroll
                for (int k = 0; k < KB; k++)
                    g_o[k*HD2+j] = tanhf(acc[k] + bb);
            }
        }
        gbar();

        // -------- C: logits = o @ W_out.T + b_out, per-block max --------
        float4* os = smem4;   // [4][256]
        for (int i = tid; i < KB*HD2; i += NT) ((float*)os)[i] = __ldcg(&g_o[i]);
        __syncthreads();
        {
            float wmax[KB] = {-FLT_MAX,-FLT_MAX,-FLT_MAX,-FLT_MAX};
            for (int v = gwarp; v < VV; v += NWARP){
                float acc[KB] = {0.f,0.f,0.f,0.f};
                const float4* w4 = (const float4*)(Wout + (size_t)v*HD2);
                #pragma unroll
                for (int q = 0; q < 8; q++){
                    int m = lane + 32*q;
                    float4 w = __ldg(&w4[m]);
                    #pragma unroll
                    for (int k = 0; k < KB; k++)
                        acc[k] += dot4(w, os[k*256+m]);
                }
                #pragma unroll
                for (int o = 16; o; o >>= 1)
                    #pragma unroll
                    for (int k = 0; k < KB; k++)
                        acc[k] += __shfl_xor_sync(0xffffffffu, acc[k], o);
                if (lane == 0){
                    float bo = __ldg(&bout[v]);
                    #pragma unroll
                    for (int k = 0; k < KB; k++){
                        float l = acc[k] + bo;
                        g_logits[(size_t)k*VV + v] = l;
                        wmax[k] = fmaxf(wmax[k], l);
                    }
                }
            }
            #pragma unroll
            for (int o = 16; o; o >>= 1)
                #pragma unroll
                for (int k = 0; k < KB; k++)
                    wmax[k] = fmaxf(wmax[k], __shfl_xor_sync(0xffffffffu, wmax[k], o));
            if (lane == 0)
                #pragma unroll
                for (int k = 0; k < KB; k++) sred[wid*KB+k] = wmax[k];
            __syncthreads();
            if (tid < KB){
                float m = -FLT_MAX;
                #pragma unroll
                for (int w = 0; w < 8; w++) m = fmaxf(m, sred[w*KB+tid]);
                g_pmax[bid*KB+tid] = m;
            }
        }
        gbar();

        // -------- D: global max + partial FTZ exp-sums --------
        if (tid < KB){
            float m = -FLT_MAX;
            for (int b = 0; b < NB; b++) m = fmaxf(m, __ldcg(&g_pmax[b*KB+tid]));
            s_gmax[tid] = m;
        }
        __syncthreads();
        {
            float lsum[KB] = {0.f,0.f,0.f,0.f};
            for (int v = bid*NT + tid; v < VV; v += NB*NT){
                #pragma unroll
                for (int k = 0; k < KB; k++)
                    lsum[k] += ftz(expf(__ldcg(&g_logits[(size_t)k*VV+v]) - s_gmax[k]));
            }
            #pragma unroll
            for (int o = 16; o; o >>= 1)
                #pragma unroll
                for (int k = 0; k < KB; k++)
                    lsum[k] += __shfl_xor_sync(0xffffffffu, lsum[k], o);
            if (lane == 0)
                #pragma unroll
                for (int k = 0; k < KB; k++) sred[wid*KB+k] = lsum[k];
            __syncthreads();
            if (tid < KB){
                float s = 0.f;
                #pragma unroll
                for (int w = 0; w < 8; w++) s += sred[w*KB+tid];
                g_psum[bid*KB+tid] = s;
            }
        }
        gbar();

        // -------- E: sc = ftz(bp * ftz(ftz(exp)/S)), per-block top-4 --------
        if (tid < KB){
            float s = 0.f;
            for (int b = 0; b < NB; b++) s += __ldcg(&g_psum[b*KB+tid]);
            s_S[tid] = s;
            s_bpold[tid] = __ldcg(&g_bp[tid]);
        }
        __syncthreads();
        {
            float tv[4] = {-FLT_MAX,-FLT_MAX,-FLT_MAX,-FLT_MAX};
            int   ti[4] = {0x7fffffff,0x7fffffff,0x7fffffff,0x7fffffff};
            for (int v = bid*NT + tid; v < VV; v += NB*NT){
                #pragma unroll
                for (int k = 0; k < KB; k++){
                    float l  = __ldcg(&g_logits[(size_t)k*VV+v]);
                    float e  = ftz(expf(l - s_gmax[k]));
                    float pf = ftz(__fdiv_rn(e, s_S[k]));
                    float sc = ftz(__fmul_rn(s_bpold[k], pf));
                    ins4(sc, k*VV+v, tv, ti);
                }
            }
            warp_merge4(tv, ti);
            if (lane == 0)
                #pragma unroll
                for (int j = 0; j < 4; j++){ scv[wid*4+j]=tv[j]; sci[wid*4+j]=ti[j]; }
            __syncthreads();
            if (tid == 0){
                float bv[4] = {-FLT_MAX,-FLT_MAX,-FLT_MAX,-FLT_MAX};
                int   bix[4] = {0x7fffffff,0x7fffffff,0x7fffffff,0x7fffffff};
                for (int i = 0; i < 32; i++) ins4(scv[i], sci[i], bv, bix);
                #pragma unroll
                for (int j = 0; j < 4; j++){ g_candv[bid*4+j]=bv[j]; g_candi[bid*4+j]=bix[j]; }
            }
        }
        gbar();

        // -------- F: block 0 selects global top-4, reorders beams --------
        if (bid == 0){
            if (wid == 0){
                float tv[4] = {-FLT_MAX,-FLT_MAX,-FLT_MAX,-FLT_MAX};
                int   ti[4] = {0x7fffffff,0x7fffffff,0x7fffffff,0x7fffffff};
                for (int i = lane; i < NB*KB; i += 32)
                    ins4(__ldcg(&g_candv[i]), __ldcg(&g_candi[i]), tv, ti);
                warp_merge4(tv, ti);
                if (lane == 0){
                    #pragma unroll
                    for (int j = 0; j < 4; j++){
                        int idx = ti[j];
                        s_bi[j] = idx / VV;
                        s_nt[j] = idx - (idx/VV)*VV;
                        g_bp[j] = tv[j];
                    }
                }
            }
            __syncthreads();
            const int nxt = (t+1)&1;
            if (tid < KB*(ML+1)){
                int kk = tid/(ML+1), col = tid%(ML+1);
                int val = (col == t+1) ? s_nt[kk]
                                       : __ldcg(&g_tok[cur][s_bi[kk]*(ML+1)+col]);
                g_tok[nxt][kk*(ML+1)+col] = val;
            }
            for (int i = tid; i < KB*HD2; i += NT){
                int kk = i>>10, j = i&1023;
                g_h[i] = __ldcg(&g_h2[(size_t)s_bi[kk]*HD2 + j]);
                g_c[i] = __ldcg(&g_c2[(size_t)s_bi[kk]*HD2 + j]);
            }
        }
        gbar();
    }

    // =============== output: tokens (4x21) then bp (4), as float32 ===============
    if (bid == 0){
        if (tid < KB*(ML+1)) out[tid] = (float)__ldcg(&g_tok[0][tid]);  // ML even -> buf 0
        if (out_size >= KB*(ML+1)+KB && tid < KB)
            out[KB*(ML+1)+tid] = __ldcg(&g_bp[tid]);
    }
}

// ---------------- host ----------------
static int pick_idx(const int* sz, int n, int want, int occ){
    int c = 0;
    for (int i = 0; i < n; i++)
        if (sz[i] == want){ if (c == occ) return i; c++; }
    return -1;
}

extern "C" void kernel_launch(void* const* d_in, const int* in_sizes, int n_in,
                              void* d_out, int out_size)
{
    int iv   = pick_idx(in_sizes, n_in, TT*DIN, 0);
    int ie   = pick_idx(in_sizes, n_in, VV*HD2, 0);
    int iWf  = pick_idx(in_sizes, n_in, GE*DIN, 0);
    int iHf  = pick_idx(in_sizes, n_in, GE*HH, 0);
    int ibf  = pick_idx(in_sizes, n_in, GE, 0);
    int iWb  = pick_idx(in_sizes, n_in, GE*DIN, 1);
    int ibb  = pick_idx(in_sizes, n_in, GE, 1);
    int idW  = pick_idx(in_sizes, n_in, 4*HD2*HD2, 0);
    int idH  = pick_idx(in_sizes, n_in, 4*HD2*HD2, 1);
    int idb  = pick_idx(in_sizes, n_in, 4*HD2, 0);
    int iWc  = pick_idx(in_sizes, n_in, HD2*2*HD2, 0);
    int ibc  = pick_idx(in_sizes, n_in, HD2, 0);
    int iWo  = pick_idx(in_sizes, n_in, VV*HD2, 1);
    int ibo  = pick_idx(in_sizes, n_in, VV, 0);
    if (iv<0||ie<0||iWf<0||iHf<0||ibf<0||iWb<0||ibb<0||idW<0||idH<0||idb<0||iWc<0||ibc<0||iWo<0||ibo<0){
        iv=0; ie=1; iWf=2; iHf=3; ibf=4; iWb=5; ibb=7; idW=8; idH=9; idb=10; iWc=11; ibc=12; iWo=13; ibo=14;
    }
    beam_kernel<<<NB, NT>>>(
        (const float*)d_in[iv],  (const float*)d_in[ie],
        (const float*)d_in[iWf], (const float*)d_in[iHf], (const float*)d_in[ibf],
        (const float*)d_in[iWb], (const float*)d_in[ibb],
        (const float*)d_in[idW], (const float*)d_in[idH], (const float*)d_in[idb],
        (const float*)d_in[iWc], (const float*)d_in[ibc],
        (const float*)d_in[iWo], (const float*)d_in[ibo],
        (float*)d_out, out_size);
}

// round 12
// speedup vs baseline: 5.6152x; 1.1648x over previous
#include <cuda_runtime.h>
#include <math.h>
#include <float.h>
#include <stdint.h>

#define TT   80
#define DIN  4096
#define HH   512
#define HD2  1024
#define GE   2048      /* 4*HH  */
#define VV   32000
#define KB   4
#define ML   20
#define NB   132
#define NT   256
#define NWARP (NB*8)   /* 1056 */

// ---------------- device scratch ----------------
__device__ float g_Xpre[TT*GE];            // video @ Wih_f.T + b_f
__device__ float g_Gb[GE];                 // video[79] @ Wih_b.T + b_b
__device__ float g_encH[2][HH];
__device__ float g_encC[HH];
__device__ float g_h2[2][KB*HD2];          // ping-pong decoder hidden
__device__ float g_c2[2][KB*HD2];
__device__ float g_o[KB*HD2];
__device__ float g_logits[KB*VV];
__device__ int   g_tok[2][KB*(ML+1)];
__device__ float g_pmax[NB*KB];
__device__ float g_psum[NB*KB];
__device__ float g_candv[NB*KB];
__device__ int   g_candi[NB*KB];
__device__ unsigned g_cnt = 0;
__device__ volatile unsigned g_epoch = 0;
__device__ unsigned g_cnt_e = 0;           // encoder sub-barrier (64 blocks)
__device__ volatile unsigned g_epoch_e = 0;

// ---------------- helpers ----------------
__device__ __forceinline__ float sigm(float x){ return 1.f/(1.f+expf(-x)); }
__device__ __forceinline__ float dot4(float4 a, float4 b){
    return a.x*b.x + a.y*b.y + a.z*b.z + a.w*b.w;
}
// FTZ: XLA fp32 flushes subnormal results to zero (THE critical semantic)
__device__ __forceinline__ float ftz(float x){
    return (fabsf(x) < FLT_MIN) ? 0.f : x;
}
__device__ __forceinline__ float4 ldcs4(const float4* p){
    float4 v;
    asm volatile("ld.global.cs.v4.f32 {%0,%1,%2,%3}, [%4];"
                 : "=f"(v.x), "=f"(v.y), "=f"(v.z), "=f"(v.w) : "l"(p));
    return v;
}

// lax.top_k ordering: larger value first; ties -> smaller flat index first
__device__ __forceinline__ bool bet(float v1,int i1,float v2,int i2){
    return (v1 > v2) || (v1 == v2 && i1 < i2);
}
__device__ __forceinline__ void ins4(float v,int i,float tv[4],int ti[4]){
    if (bet(v,i,tv[3],ti[3])){
        tv[3]=v; ti[3]=i;
        if (bet(tv[3],ti[3],tv[2],ti[2])){ float a=tv[2];int b=ti[2]; tv[2]=tv[3];ti[2]=ti[3]; tv[3]=a;ti[3]=b; }
        if (bet(tv[2],ti[2],tv[1],ti[1])){ float a=tv[1];int b=ti[1]; tv[1]=tv[2];ti[1]=ti[2]; tv[2]=a;ti[2]=b; }
        if (bet(tv[1],ti[1],tv[0],ti[0])){ float a=tv[0];int b=ti[0]; tv[0]=tv[1];ti[0]=ti[1]; tv[1]=a;ti[1]=b; }
    }
}
__device__ __forceinline__ void warp_merge4(float tv[4],int ti[4]){
    #pragma unroll
    for (int off=16; off; off>>=1){
        float ov[4]; int oi[4];
        #pragma unroll
        for (int j=0;j<4;j++){
            ov[j]=__shfl_xor_sync(0xffffffffu,tv[j],off);
            oi[j]=__shfl_xor_sync(0xffffffffu,ti[j],off);
        }
        #pragma unroll
        for (int j=0;j<4;j++) ins4(ov[j],oi[j],tv,ti);
    }
}

// grid-wide barrier, release/acquire correct, replay-safe
__device__ __forceinline__ void gbar(){
    __threadfence();
    __syncthreads();
    if (threadIdx.x == 0){
        unsigned e = g_epoch;
        if (atomicAdd(&g_cnt, 1u) == NB-1u){
            g_cnt = 0;
            __threadfence();
            g_epoch = e + 1u;
        } else {
            while (g_epoch == e) { __nanosleep(64); }
        }
    }
    __syncthreads();
    __threadfence();
}

__global__ void __launch_bounds__(NT, 1) beam_kernel(
    const float* __restrict__ video, const float* __restrict__ emb,
    const float* __restrict__ Wih_f, const float* __restrict__ Whh_f, const float* __restrict__ b_f,
    const float* __restrict__ Wih_b, const float* __restrict__ b_b,
    const float* __restrict__ dWih, const float* __restrict__ dWhh, const float* __restrict__ db,
    const float* __restrict__ Wcat, const float* __restrict__ bcat,
    const float* __restrict__ Wout, const float* __restrict__ bout,
    float* __restrict__ out, int out_size)
{
    __shared__ float4 smem4[2048];           // 32 KB staging
    float* smem = (float*)smem4;
    __shared__ float sm_m[8][KB], sm_s[8][KB];
    __shared__ float scv[8*KB];  __shared__ int sci[8*KB];
    __shared__ int   s_bi2[KB], s_tok[KB];
    __shared__ float s_bp[KB], s_gmax[KB], s_S[KB];

    const int bid = blockIdx.x, tid = threadIdx.x;
    const int wid = tid>>5, lane = tid&31;
    const int gwarp = bid*8 + wid;

    // =============== P0: init + encoder input projections ===============
    {
        int g = bid*NT + tid;
        if (g < KB*(ML+1)) g_tok[0][g] = 1;                 // BOS
        if (g < HH) { g_encH[0][g] = 0.f; g_encC[g] = 0.f; }
    }

    for (int job = bid; job < 168; job += NB){
        if (job < 160){
            const int t0 = (job>>5)*16, j0 = (job&31)*64;
            float* Xs = smem;                // [16][65]
            float* Ws = smem + 16*65;        // [64][65]
            const int jj = tid & 63, tr = tid >> 6;
            float acc[4] = {0.f,0.f,0.f,0.f};
            for (int kc = 0; kc < DIN; kc += 64){
                __syncthreads();
                for (int i = tid; i < 16*64; i += NT){
                    int r = i>>6, kk = i&63;
                    Xs[r*65+kk] = __ldg(&video[(size_t)(t0+r)*DIN + kc+kk]);
                }
                for (int i = tid; i < 64*64; i += NT){
                    int r = i>>6, kk = i&63;
                    Ws[r*65+kk] = __ldg(&Wih_f[(size_t)(j0+r)*DIN + kc+kk]);
                }
                __syncthreads();
                #pragma unroll 8
                for (int kk = 0; kk < 64; kk++){
                    float w = Ws[jj*65+kk];
                    #pragma unroll
                    for (int u = 0; u < 4; u++)
                        acc[u] += Xs[(tr+4*u)*65+kk]*w;
                }
            }
            float bb = __ldg(&b_f[j0+jj]);
            #pragma unroll
            for (int u = 0; u < 4; u++)
                g_Xpre[(size_t)(t0+tr+4*u)*GE + j0+jj] = acc[u] + bb;
            __syncthreads();
        } else {
            const int r0 = (job-160)*256 + wid*32;
            const float4* x4 = (const float4*)(video + (size_t)(TT-1)*DIN);
            for (int rr = 0; rr < 32; rr++){
                int row = r0 + rr;
                const float4* w4 = (const float4*)(Wih_b + (size_t)row*DIN);
                float a = 0.f;
                #pragma unroll 8
                for (int q = 0; q < 32; q++)
                    a += dot4(__ldg(&w4[lane+32*q]), __ldg(&x4[lane+32*q]));
                #pragma unroll
                for (int o = 16; o; o >>= 1) a += __shfl_xor_sync(0xffffffffu,a,o);
                if (lane == 0) g_Gb[row] = a + __ldg(&b_b[row]);
            }
        }
    }
    unsigned e0 = g_epoch_e;    // snapshot BEFORE the barrier (no bumps yet this launch)
    gbar();

    // =============== P1: forward encoder (80 steps, blocks 0-63 only) ===============
    if (bid < 64){
        unsigned e = e0;
        for (int t = 0; t < TT; t++){
            const float* hin = g_encH[t&1];
            for (int i = tid; i < HH; i += NT) smem[i] = __ldcg(&hin[i]);
            __syncthreads();
            const int j = bid*8 + wid;       // 0..511
            const float4* h4 = (const float4*)smem;
            float acc[4];
            #pragma unroll
            for (int g = 0; g < 4; g++){
                const float4* w4 = (const float4*)(Whh_f + (size_t)(g*HH + j)*HH);
                float a = 0.f;
                #pragma unroll
                for (int q = 0; q < 4; q++)
                    a += dot4(__ldg(&w4[lane+32*q]), h4[lane+32*q]);
                acc[g] = a;
            }
            #pragma unroll
            for (int o = 16; o; o >>= 1)
                #pragma unroll
                for (int g = 0; g < 4; g++)
                    acc[g] += __shfl_xor_sync(0xffffffffu, acc[g], o);
            if (lane == 0){
                float gi = acc[0] + __ldcg(&g_Xpre[(size_t)t*GE + j]);
                float gf = acc[1] + __ldcg(&g_Xpre[(size_t)t*GE + HH + j]);
                float gg = acc[2] + __ldcg(&g_Xpre[(size_t)t*GE + 2*HH + j]);
                float go = acc[3] + __ldcg(&g_Xpre[(size_t)t*GE + 3*HH + j]);
                float c2 = sigm(gf)*__ldcg(&g_encC[j]) + sigm(gi)*tanhf(gg);
                float h2 = sigm(go)*tanhf(c2);
                g_encC[j] = c2;
                g_encH[(t+1)&1][j] = h2;
            }
            // 64-block sub-barrier
            __threadfence();
            __syncthreads();
            if (tid == 0){
                if (atomicAdd(&g_cnt_e, 1u) == 63u){
                    g_cnt_e = 0;
                    __threadfence();
                    g_epoch_e = e + 1u;
                } else {
                    while (g_epoch_e == e) { __nanosleep(32); }
                }
            }
            __syncthreads();
            __threadfence();
            e = e + 1u;
        }
    } else {
        if (tid == 0){
            while ((unsigned)(g_epoch_e - e0) < (unsigned)TT) { __nanosleep(256); }
        }
        __syncthreads();
        __threadfence();
    }
    gbar();

    // =============== P2: decoder init: h0=[hf,hb] into buffer 0, c=0 ===============
    {
        int g = bid*NT + tid;
        if (g < HH){
            float hf = __ldcg(&g_encH[0][g]);   // TT even -> buf 0
            float gi = __ldcg(&g_Gb[g]);
            float gg = __ldcg(&g_Gb[2*HH+g]);
            float go = __ldcg(&g_Gb[3*HH+g]);
            float cb = sigm(gi)*tanhf(gg);      // c0=0
            float hb = sigm(go)*tanhf(cb);
            #pragma unroll
            for (int k = 0; k < KB; k++){
                g_h2[0][k*HD2 + g]      = hf;
                g_h2[0][k*HD2 + HH + g] = hb;
            }
        }
        for (int i = g; i < KB*HD2; i += NB*NT) g_c2[0][i] = 0.f;
    }
    gbar();

    // =============== P3: decoder beam search (20 steps) ===============
    float4* xs = smem4;            // [4][256] f4 = x
    float4* hs = smem4 + 4*256;    // [4][256] f4 = h/h2

    for (int t = 0; t < ML; t++){
        const int cur = t & 1, nxt = (t+1) & 1;

        // -------- SEL: every block redundantly resolves the beam selection --------
        if (t == 0){
            if (tid < KB){ s_bi2[tid]=tid; s_tok[tid]=1; s_bp[tid]=(tid==0)?1.f:0.f; }
            __syncthreads();
        } else {
            if (wid == 0){
                float tv[4] = {-FLT_MAX,-FLT_MAX,-FLT_MAX,-FLT_MAX};
                int   ti[4] = {0x7fffffff,0x7fffffff,0x7fffffff,0x7fffffff};
                for (int i = lane; i < NB*KB; i += 32)
                    ins4(__ldcg(&g_candv[i]), __ldcg(&g_candi[i]), tv, ti);
                warp_merge4(tv, ti);
                if (lane == 0)
                    #pragma unroll
                    for (int j = 0; j < 4; j++){
                        int idx = ti[j];
                        s_bi2[j] = idx / VV;
                        s_tok[j] = idx - (idx/VV)*VV;
                        s_bp[j]  = tv[j];
                    }
            }
            __syncthreads();
            if (bid == 0 && tid < KB*(ML+1)){   // token history (block 0 only)
                int kk = tid/(ML+1), col = tid%(ML+1);
                int val = (col == t) ? s_tok[kk]
                                     : g_tok[(t-1)&1][s_bi2[kk]*(ML+1)+col];
                g_tok[t&1][tid] = val;
            }
        }

        // -------- A: decoder LSTM cell (gathers prev state by beam) --------
        for (int i = tid; i < KB*HD2; i += NT){
            int k = i>>10, j = i&1023;
            ((float*)xs)[i] = __ldg(&emb[(size_t)s_tok[k]*HD2 + j]);
            ((float*)hs)[i] = __ldcg(&g_h2[cur][s_bi2[k]*HD2 + j]);
        }
        __syncthreads();
        for (int j = gwarp; j < HD2; j += NWARP){
            float acc[4][KB];
            #pragma unroll
            for (int g = 0; g < 4; g++)
                #pragma unroll
                for (int k = 0; k < KB; k++) acc[g][k] = 0.f;
            #pragma unroll 2
            for (int q = 0; q < 8; q++){
                int m = lane + 32*q;
                #pragma unroll
                for (int g = 0; g < 4; g++){
                    float4 wi = __ldg((const float4*)(dWih + (size_t)(g*HD2+j)*HD2) + m);
                    float4 wh = __ldg((const float4*)(dWhh + (size_t)(g*HD2+j)*HD2) + m);
                    #pragma unroll
                    for (int k = 0; k < KB; k++)
                        acc[g][k] += dot4(wi, xs[k*256+m]) + dot4(wh, hs[k*256+m]);
                }
            }
            #pragma unroll
            for (int o = 16; o; o >>= 1)
                #pragma unroll
                for (int g = 0; g < 4; g++)
                    #pragma unroll
                    for (int k = 0; k < KB; k++)
                        acc[g][k] += __shfl_xor_sync(0xffffffffu, acc[g][k], o);
            if (lane == 0){
                float bi_ = __ldg(&db[j]),       bf_ = __ldg(&db[HD2+j]);
                float bg_ = __ldg(&db[2*HD2+j]), bo_ = __ldg(&db[3*HD2+j]);
                #pragma unroll
                for (int k = 0; k < KB; k++){
                    float gi = acc[0][k]+bi_, gf = acc[1][k]+bf_;
                    float gg = acc[2][k]+bg_, go = acc[3][k]+bo_;
                    float cp = __ldcg(&g_c2[cur][s_bi2[k]*HD2 + j]);
                    float c2 = sigm(gf)*cp + sigm(gi)*tanhf(gg);
                    float h2 = sigm(go)*tanhf(c2);
                    g_c2[nxt][k*HD2+j] = c2;
                    g_h2[nxt][k*HD2+j] = h2;
                }
            }
        }
        gbar();

        // -------- B: o = tanh(W_cat @ [h2, x] + b_cat) --------
        for (int i = tid; i < KB*HD2; i += NT) ((float*)hs)[i] = __ldcg(&g_h2[nxt][i]);
        __syncthreads();
        for (int j = gwarp; j < HD2; j += NWARP){
            float acc[KB] = {0.f,0.f,0.f,0.f};
            const float4* wr = (const float4*)(Wcat + (size_t)j*(2*HD2));
            #pragma unroll 2
            for (int q = 0; q < 8; q++){
                int m = lane + 32*q;
                float4 w1 = __ldg(&wr[m]);
                float4 w2 = __ldg(&wr[256+m]);
                #pragma unroll
                for (int k = 0; k < KB; k++)
                    acc[k] += dot4(w1, hs[k*256+m]) + dot4(w2, xs[k*256+m]);
            }
            #pragma unroll
            for (int o = 16; o; o >>= 1)
                #pragma unroll
                for (int k = 0; k < KB; k++)
                    acc[k] += __shfl_xor_sync(0xffffffffu, acc[k], o);
            if (lane == 0){
                float bb = __ldg(&bcat[j]);
                #pragma unroll
                for (int k = 0; k < KB; k++)
                    g_o[k*HD2+j] = tanhf(acc[k] + bb);
            }
        }
        gbar();

        // -------- C: logits (4 rows/warp, streaming Wout) + online (max,expsum) --------
        float4* os = smem4;   // [4][256]
        for (int i = tid; i < KB*HD2; i += NT) ((float*)os)[i] = __ldcg(&g_o[i]);
        __syncthreads();
        {
            float mw[KB] = {-FLT_MAX,-FLT_MAX,-FLT_MAX,-FLT_MAX};
            float sw[KB] = {0.f,0.f,0.f,0.f};
            for (int v0 = gwarp*4; v0 < VV; v0 += NWARP*4){
                float acc[4][KB];
                #pragma unroll
                for (int r = 0; r < 4; r++)
                    #pragma unroll
                    for (int k = 0; k < KB; k++) acc[r][k] = 0.f;
                #pragma unroll 2
                for (int q = 0; q < 8; q++){
                    int m = lane + 32*q;
                    float4 o0 = os[0*256+m], o1 = os[1*256+m];
                    float4 o2 = os[2*256+m], o3 = os[3*256+m];
                    #pragma unroll
                    for (int r = 0; r < 4; r++){
                        float4 w = ldcs4((const float4*)(Wout + (size_t)(v0+r)*HD2) + m);
                        acc[r][0] += dot4(w, o0);
                        acc[r][1] += dot4(w, o1);
                        acc[r][2] += dot4(w, o2);
                        acc[r][3] += dot4(w, o3);
                    }
                }
                #pragma unroll
                for (int o = 16; o; o >>= 1)
                    #pragma unroll
                    for (int r = 0; r < 4; r++)
                        #pragma unroll
                        for (int k = 0; k < KB; k++)
                            acc[r][k] += __shfl_xor_sync(0xffffffffu, acc[r][k], o);
                if (lane == 0){
                    #pragma unroll
                    for (int r = 0; r < 4; r++){
                        float bo = __ldg(&bout[v0+r]);
                        #pragma unroll
                        for (int k = 0; k < KB; k++){
                            float l = acc[r][k] + bo;
                            g_logits[(size_t)k*VV + v0 + r] = l;
                            if (l > mw[k]){ sw[k] = sw[k]*expf(mw[k]-l) + 1.f; mw[k] = l; }
                            else          { sw[k] += expf(l - mw[k]); }
                        }
                    }
                }
            }
            if (lane == 0)
                #pragma unroll
                for (int k = 0; k < KB; k++){ sm_m[wid][k] = mw[k]; sm_s[wid][k] = sw[k]; }
            __syncthreads();
            if (tid < KB){
                const int k = tid;
                float m = -FLT_MAX, s = 0.f;
                #pragma unroll
                for (int w = 0; w < 8; w++){
                    float mwv = sm_m[w][k], swv = sm_s[w][k];
                    if (mwv > m){ s = s*expf(m-mwv) + swv; m = mwv; }
                    else        { s += swv*expf(mwv-m); }
                }
                g_pmax[bid*KB+k] = m;
                g_psum[bid*KB+k] = s;
            }
        }
        gbar();

        // -------- E: global (m,S); sc=ftz chain; per-block top-4 --------
        if (wid < KB){
            const int k = wid;
            float mloc = -FLT_MAX;
            for (int i = lane; i < NB; i += 32)
                mloc = fmaxf(mloc, __ldcg(&g_pmax[i*KB+k]));
            #pragma unroll
            for (int o = 16; o; o >>= 1) mloc = fmaxf(mloc, __shfl_xor_sync(0xffffffffu, mloc, o));
            float sloc = 0.f;
            for (int i = lane; i < NB; i += 32){
                float mb = __ldcg(&g_pmax[i*KB+k]);
                float sb = __ldcg(&g_psum[i*KB+k]);
                sloc += sb*expf(mb - mloc);
            }
            #pragma unroll
            for (int o = 16; o; o >>= 1) sloc += __shfl_xor_sync(0xffffffffu, sloc, o);
            if (lane == 0){ s_gmax[k] = mloc; s_S[k] = sloc; }
        }
        __syncthreads();
        {
            float tv[4] = {-FLT_MAX,-FLT_MAX,-FLT_MAX,-FLT_MAX};
            int   ti[4] = {0x7fffffff,0x7fffffff,0x7fffffff,0x7fffffff};
            for (int v = bid*NT + tid; v < VV; v += NB*NT){
                #pragma unroll
                for (int k = 0; k < KB; k++){
                    float l  = __ldcg(&g_logits[(size_t)k*VV+v]);
                    float e  = ftz(expf(l - s_gmax[k]));
                    float pf = ftz(__fdiv_rn(e, s_S[k]));
                    float sc = ftz(__fmul_rn(s_bp[k], pf));
                    ins4(sc, k*VV+v, tv, ti);
                }
            }
            warp_merge4(tv, ti);
            if (lane == 0)
                #pragma unroll
                for (int j = 0; j < 4; j++){ scv[wid*4+j]=tv[j]; sci[wid*4+j]=ti[j]; }
            __syncthreads();
            if (tid == 0){
                float bv[4] = {-FLT_MAX,-FLT_MAX,-FLT_MAX,-FLT_MAX};
                int   bix[4] = {0x7fffffff,0x7fffffff,0x7fffffff,0x7fffffff};
                for (int i = 0; i < 32; i++) ins4(scv[i], sci[i], bv, bix);
                #pragma unroll
                for (int j = 0; j < 4; j++){ g_candv[bid*4+j]=bv[j]; g_candi[bid*4+j]=bix[j]; }
            }
        }
        gbar();
    }

    // =============== final selection + output ===============
    if (wid == 0){
        float tv[4] = {-FLT_MAX,-FLT_MAX,-FLT_MAX,-FLT_MAX};
        int   ti[4] = {0x7fffffff,0x7fffffff,0x7fffffff,0x7fffffff};
        for (int i = lane; i < NB*KB; i += 32)
            ins4(__ldcg(&g_candv[i]), __ldcg(&g_candi[i]), tv, ti);
        warp_merge4(tv, ti);
        if (lane == 0)
            #pragma unroll
            for (int j = 0; j < 4; j++){
                int idx = ti[j];
                s_bi2[j] = idx / VV;
                s_tok[j] = idx - (idx/VV)*VV;
                s_bp[j]  = tv[j];
            }
    }
    __syncthreads();
    if (bid == 0){
        if (tid < KB*(ML+1)){
            int kk = tid/(ML+1), col = tid%(ML+1);
            int val = (col == ML) ? s_tok[kk]
                                  : g_tok[(ML-1)&1][s_bi2[kk]*(ML+1)+col];
            out[tid] = (float)val;
        }
        if (out_size >= KB*(ML+1)+KB && tid < KB)
            out[KB*(ML+1)+tid] = s_bp[tid];
    }
}

// ---------------- host ----------------
static int pick_idx(const int* sz, int n, int want, int occ){
    int c = 0;
    for (int i = 0; i < n; i++)
        if (sz[i] == want){ if (c == occ) return i; c++; }
    return -1;
}

extern "C" void kernel_launch(void* const* d_in, const int* in_sizes, int n_in,
                              void* d_out, int out_size)
{
    int iv   = pick_idx(in_sizes, n_in, TT*DIN, 0);
    int ie   = pick_idx(in_sizes, n_in, VV*HD2, 0);
    int iWf  = pick_idx(in_sizes, n_in, GE*DIN, 0);
    int iHf  = pick_idx(in_sizes, n_in, GE*HH, 0);
    int ibf  = pick_idx(in_sizes, n_in, GE, 0);
    int iWb  = pick_idx(in_sizes, n_in, GE*DIN, 1);
    int ibb  = pick_idx(in_sizes, n_in, GE, 1);
    int idW  = pick_idx(in_sizes, n_in, 4*HD2*HD2, 0);
    int idH  = pick_idx(in_sizes, n_in, 4*HD2*HD2, 1);
    int idb  = pick_idx(in_sizes, n_in, 4*HD2, 0);
    int iWc  = pick_idx(in_sizes, n_in, HD2*2*HD2, 0);
    int ibc  = pick_idx(in_sizes, n_in, HD2, 0);
    int iWo  = pick_idx(in_sizes, n_in, VV*HD2, 1);
    int ibo  = pick_idx(in_sizes, n_in, VV, 0);
    if (iv<0||ie<0||iWf<0||iHf<0||ibf<0||iWb<0||ibb<0||idW<0||idH<0||idb<0||iWc<0||ibc<0||iWo<0||ibo<0){
        iv=0; ie=1; iWf=2; iHf=3; ibf=4; iWb=5; ibb=7; idW=8; idH=9; idb=10; iWc=11; ibc=12; iWo=13; ibo=14;
    }
    beam_kernel<<<NB, NT>>>(
        (const float*)d_in[iv],  (const float*)d_in[ie],
        (const float*)d_in[iWf], (const float*)d_in[iHf], (const float*)d_in[ibf],
        (const float*)d_in[iWb], (const float*)d_in[ibb],
        (const float*)d_in[idW], (const float*)d_in[idH], (const float*)d_in[idb],
        (const float*)d_in[iWc], (const float*)d_in[ibc],
        (const float*)d_in[iWo], (const float*)d_in[ibo],
        (float*)d_out, out_size);
}

// round 13
// speedup vs baseline: 5.9635x; 1.0620x over previous
#include <cuda_runtime.h>
#include <math.h>
#include <float.h>
#include <stdint.h>

#define TT   80
#define DIN  4096
#define HH   512
#define HD2  1024
#define GE   2048      /* 4*HH  */
#define VV   32000
#define KB   4
#define ML   20
#define NB   264
#define NT   256
#define NWARP (NB*8)   /* 2112 */

// ---------------- device scratch ----------------
__device__ float g_Xpre[TT*GE];            // video @ Wih_f.T + b_f
__device__ float g_Gb[GE];                 // video[79] @ Wih_b.T + b_b
__device__ float g_encH[2][HH];
__device__ float g_encC[HH];
__device__ float g_h2[2][KB*HD2];          // ping-pong decoder hidden
__device__ float g_c2[2][KB*HD2];
__device__ float g_o[KB*HD2];
__device__ float g_logits[KB*VV];
__device__ int   g_tok[2][KB*(ML+1)];
__device__ float g_pmax[NB*KB];
__device__ float g_psum[NB*KB];
__device__ float g_candv[NB*KB];
__device__ int   g_candi[NB*KB];
__device__ unsigned g_cnt = 0;
__device__ volatile unsigned g_epoch = 0;
__device__ unsigned g_cnt_e = 0;           // encoder sub-barrier (64 blocks)
__device__ volatile unsigned g_epoch_e = 0;

// ---------------- helpers ----------------
__device__ __forceinline__ float sigm(float x){ return 1.f/(1.f+expf(-x)); }
__device__ __forceinline__ float dot4(float4 a, float4 b){
    return a.x*b.x + a.y*b.y + a.z*b.z + a.w*b.w;
}
// FTZ: XLA fp32 flushes subnormal results to zero (THE critical semantic)
__device__ __forceinline__ float ftz(float x){
    return (fabsf(x) < FLT_MIN) ? 0.f : x;
}
__device__ __forceinline__ float4 ldcs4(const float4* p){
    float4 v;
    asm volatile("ld.global.cs.v4.f32 {%0,%1,%2,%3}, [%4];"
                 : "=f"(v.x), "=f"(v.y), "=f"(v.z), "=f"(v.w) : "l"(p));
    return v;
}

// lax.top_k ordering: larger value first; ties -> smaller flat index first
__device__ __forceinline__ bool bet(float v1,int i1,float v2,int i2){
    return (v1 > v2) || (v1 == v2 && i1 < i2);
}
__device__ __forceinline__ void ins4(float v,int i,float tv[4],int ti[4]){
    if (bet(v,i,tv[3],ti[3])){
        tv[3]=v; ti[3]=i;
        if (bet(tv[3],ti[3],tv[2],ti[2])){ float a=tv[2];int b=ti[2]; tv[2]=tv[3];ti[2]=ti[3]; tv[3]=a;ti[3]=b; }
        if (bet(tv[2],ti[2],tv[1],ti[1])){ float a=tv[1];int b=ti[1]; tv[1]=tv[2];ti[1]=ti[2]; tv[2]=a;ti[2]=b; }
        if (bet(tv[1],ti[1],tv[0],ti[0])){ float a=tv[0];int b=ti[0]; tv[0]=tv[1];ti[0]=ti[1]; tv[1]=a;ti[1]=b; }
    }
}
__device__ __forceinline__ void warp_merge4(float tv[4],int ti[4]){
    #pragma unroll
    for (int off=16; off; off>>=1){
        float ov[4]; int oi[4];
        #pragma unroll
        for (int j=0;j<4;j++){
            ov[j]=__shfl_xor_sync(0xffffffffu,tv[j],off);
            oi[j]=__shfl_xor_sync(0xffffffffu,ti[j],off);
        }
        #pragma unroll
        for (int j=0;j<4;j++) ins4(ov[j],oi[j],tv,ti);
    }
}

// grid-wide barrier, release/acquire correct, replay-safe
__device__ __forceinline__ void gbar(){
    __threadfence();
    __syncthreads();
    if (threadIdx.x == 0){
        unsigned e = g_epoch;
        if (atomicAdd(&g_cnt, 1u) == NB-1u){
            g_cnt = 0;
            __threadfence();
            g_epoch = e + 1u;
        } else {
            while (g_epoch == e) { __nanosleep(32); }
        }
    }
    __syncthreads();
    __threadfence();
}

__global__ void __launch_bounds__(NT, 2) beam_kernel(
    const float* __restrict__ video, const float* __restrict__ emb,
    const float* __restrict__ Wih_f, const float* __restrict__ Whh_f, const float* __restrict__ b_f,
    const float* __restrict__ Wih_b, const float* __restrict__ b_b,
    const float* __restrict__ dWih, const float* __restrict__ dWhh, const float* __restrict__ db,
    const float* __restrict__ Wcat, const float* __restrict__ bcat,
    const float* __restrict__ Wout, const float* __restrict__ bout,
    float* __restrict__ out, int out_size)
{
    __shared__ float4 smem4[2048];           // 32 KB staging
    float* smem = (float*)smem4;
    __shared__ float sm_m[8][KB], sm_s[8][KB];
    __shared__ float scv[8*KB];  __shared__ int sci[8*KB];
    __shared__ int   s_bi2[KB], s_tok[KB];
    __shared__ float s_bp[KB], s_gmax[KB], s_S[KB];

    const int bid = blockIdx.x, tid = threadIdx.x;
    const int wid = tid>>5, lane = tid&31;
    const int gwarp = bid*8 + wid;

    // =============== P0: init + encoder input projections ===============
    {
        int g = bid*NT + tid;
        if (g < KB*(ML+1)) g_tok[0][g] = 1;                 // BOS
        if (g < HH) { g_encH[0][g] = 0.f; g_encC[g] = 0.f; }
    }

    for (int job = bid; job < 168; job += NB){
        if (job < 160){
            const int t0 = (job>>5)*16, j0 = (job&31)*64;
            float* Xs = smem;                // [16][65]
            float* Ws = smem + 16*65;        // [64][65]
            const int jj = tid & 63, tr = tid >> 6;
            float acc[4] = {0.f,0.f,0.f,0.f};
            for (int kc = 0; kc < DIN; kc += 64){
                __syncthreads();
                for (int i = tid; i < 16*64; i += NT){
                    int r = i>>6, kk = i&63;
                    Xs[r*65+kk] = __ldg(&video[(size_t)(t0+r)*DIN + kc+kk]);
                }
                for (int i = tid; i < 64*64; i += NT){
                    int r = i>>6, kk = i&63;
                    Ws[r*65+kk] = __ldg(&Wih_f[(size_t)(j0+r)*DIN + kc+kk]);
                }
                __syncthreads();
                #pragma unroll 8
                for (int kk = 0; kk < 64; kk++){
                    float w = Ws[jj*65+kk];
                    #pragma unroll
                    for (int u = 0; u < 4; u++)
                        acc[u] += Xs[(tr+4*u)*65+kk]*w;
                }
            }
            float bb = __ldg(&b_f[j0+jj]);
            #pragma unroll
            for (int u = 0; u < 4; u++)
                g_Xpre[(size_t)(t0+tr+4*u)*GE + j0+jj] = acc[u] + bb;
            __syncthreads();
        } else {
            const int r0 = (job-160)*256 + wid*32;
            const float4* x4 = (const float4*)(video + (size_t)(TT-1)*DIN);
            for (int rr = 0; rr < 32; rr++){
                int row = r0 + rr;
                const float4* w4 = (const float4*)(Wih_b + (size_t)row*DIN);
                float a = 0.f;
                #pragma unroll 8
                for (int q = 0; q < 32; q++)
                    a += dot4(__ldg(&w4[lane+32*q]), __ldg(&x4[lane+32*q]));
                #pragma unroll
                for (int o = 16; o; o >>= 1) a += __shfl_xor_sync(0xffffffffu,a,o);
                if (lane == 0) g_Gb[row] = a + __ldg(&b_b[row]);
            }
        }
    }
    unsigned e0 = g_epoch_e;    // snapshot BEFORE the barrier
    gbar();

    // =============== P1: forward encoder (80 steps, blocks 0-63 only) ===============
    if (bid < 64){
        unsigned e = e0;
        for (int t = 0; t < TT; t++){
            const float* hin = g_encH[t&1];
            for (int i = tid; i < HH; i += NT) smem[i] = __ldcg(&hin[i]);
            __syncthreads();
            const int j = bid*8 + wid;       // 0..511
            const float4* h4 = (const float4*)smem;
            float acc[4];
            #pragma unroll
            for (int g = 0; g < 4; g++){
                const float4* w4 = (const float4*)(Whh_f + (size_t)(g*HH + j)*HH);
                float a = 0.f;
                #pragma unroll
                for (int q = 0; q < 4; q++)
                    a += dot4(__ldg(&w4[lane+32*q]), h4[lane+32*q]);
                acc[g] = a;
            }
            #pragma unroll
            for (int o = 16; o; o >>= 1)
                #pragma unroll
                for (int g = 0; g < 4; g++)
                    acc[g] += __shfl_xor_sync(0xffffffffu, acc[g], o);
            if (lane == 0){
                float gi = acc[0] + __ldcg(&g_Xpre[(size_t)t*GE + j]);
                float gf = acc[1] + __ldcg(&g_Xpre[(size_t)t*GE + HH + j]);
                float gg = acc[2] + __ldcg(&g_Xpre[(size_t)t*GE + 2*HH + j]);
                float go = acc[3] + __ldcg(&g_Xpre[(size_t)t*GE + 3*HH + j]);
                float c2 = sigm(gf)*__ldcg(&g_encC[j]) + sigm(gi)*tanhf(gg);
                float h2 = sigm(go)*tanhf(c2);
                g_encC[j] = c2;
                g_encH[(t+1)&1][j] = h2;
            }
            // 64-block sub-barrier
            __threadfence();
            __syncthreads();
            if (tid == 0){
                if (atomicAdd(&g_cnt_e, 1u) == 63u){
                    g_cnt_e = 0;
                    __threadfence();
                    g_epoch_e = e + 1u;
                } else {
                    while (g_epoch_e == e) { __nanosleep(32); }
                }
            }
            __syncthreads();
            __threadfence();
            e = e + 1u;
        }
    } else {
        if (tid == 0){
            while ((unsigned)(g_epoch_e - e0) < (unsigned)TT) { __nanosleep(256); }
        }
        __syncthreads();
        __threadfence();
    }
    gbar();

    // =============== P2: decoder init: h0=[hf,hb] into buffer 0, c=0 ===============
    {
        int g = bid*NT + tid;
        if (g < HH){
            float hf = __ldcg(&g_encH[0][g]);   // TT even -> buf 0
            float gi = __ldcg(&g_Gb[g]);
            float gg = __ldcg(&g_Gb[2*HH+g]);
            float go = __ldcg(&g_Gb[3*HH+g]);
            float cb = sigm(gi)*tanhf(gg);      // c0=0
            float hb = sigm(go)*tanhf(cb);
            #pragma unroll
            for (int k = 0; k < KB; k++){
                g_h2[0][k*HD2 + g]      = hf;
                g_h2[0][k*HD2 + HH + g] = hb;
            }
        }
        for (int i = g; i < KB*HD2; i += NB*NT) g_c2[0][i] = 0.f;
    }
    gbar();

    // =============== P3: decoder beam search (20 steps) ===============
    float4* xs = smem4;            // [4][256] f4 = x
    float4* hs = smem4 + 4*256;    // [4][256] f4 = h/h2

    for (int t = 0; t < ML; t++){
        const int cur = t & 1, nxt = (t+1) & 1;

        // -------- SEL: every block redundantly resolves the beam selection --------
        if (t == 0){
            if (tid < KB){ s_bi2[tid]=tid; s_tok[tid]=1; s_bp[tid]=(tid==0)?1.f:0.f; }
            __syncthreads();
        } else {
            if (wid == 0){
                float tv[4] = {-FLT_MAX,-FLT_MAX,-FLT_MAX,-FLT_MAX};
                int   ti[4] = {0x7fffffff,0x7fffffff,0x7fffffff,0x7fffffff};
                for (int i = lane; i < NB*KB; i += 32)
                    ins4(__ldcg(&g_candv[i]), __ldcg(&g_candi[i]), tv, ti);
                warp_merge4(tv, ti);
                if (lane == 0)
                    #pragma unroll
                    for (int j = 0; j < 4; j++){
                        int idx = ti[j];
                        s_bi2[j] = idx / VV;
                        s_tok[j] = idx - (idx/VV)*VV;
                        s_bp[j]  = tv[j];
                    }
            }
            __syncthreads();
            if (bid == 0 && tid < KB*(ML+1)){   // token history (block 0 only)
                int kk = tid/(ML+1), col = tid%(ML+1);
                int val = (col == t) ? s_tok[kk]
                                     : g_tok[(t-1)&1][s_bi2[kk]*(ML+1)+col];
                g_tok[t&1][tid] = val;
            }
        }

        // -------- A: decoder LSTM cell (gathers prev state by beam) --------
        for (int i = tid; i < KB*HD2; i += NT){
            int k = i>>10, j = i&1023;
            ((float*)xs)[i] = __ldg(&emb[(size_t)s_tok[k]*HD2 + j]);
            ((float*)hs)[i] = __ldcg(&g_h2[cur][s_bi2[k]*HD2 + j]);
        }
        __syncthreads();
        for (int j = gwarp; j < HD2; j += NWARP){
            float acc[4][KB];
            #pragma unroll
            for (int g = 0; g < 4; g++)
                #pragma unroll
                for (int k = 0; k < KB; k++) acc[g][k] = 0.f;
            #pragma unroll 2
            for (int q = 0; q < 8; q++){
                int m = lane + 32*q;
                #pragma unroll
                for (int g = 0; g < 4; g++){
                    float4 wi = __ldg((const float4*)(dWih + (size_t)(g*HD2+j)*HD2) + m);
                    float4 wh = __ldg((const float4*)(dWhh + (size_t)(g*HD2+j)*HD2) + m);
                    #pragma unroll
                    for (int k = 0; k < KB; k++)
                        acc[g][k] += dot4(wi, xs[k*256+m]) + dot4(wh, hs[k*256+m]);
                }
            }
            #pragma unroll
            for (int o = 16; o; o >>= 1)
                #pragma unroll
                for (int g = 0; g < 4; g++)
                    #pragma unroll
                    for (int k = 0; k < KB; k++)
                        acc[g][k] += __shfl_xor_sync(0xffffffffu, acc[g][k], o);
            if (lane == 0){
                float bi_ = __ldg(&db[j]),       bf_ = __ldg(&db[HD2+j]);
                float bg_ = __ldg(&db[2*HD2+j]), bo_ = __ldg(&db[3*HD2+j]);
                #pragma unroll
                for (int k = 0; k < KB; k++){
                    float gi = acc[0][k]+bi_, gf = acc[1][k]+bf_;
                    float gg = acc[2][k]+bg_, go = acc[3][k]+bo_;
                    float cp = __ldcg(&g_c2[cur][s_bi2[k]*HD2 + j]);
                    float c2 = sigm(gf)*cp + sigm(gi)*tanhf(gg);
                    float h2 = sigm(go)*tanhf(c2);
                    g_c2[nxt][k*HD2+j] = c2;
                    g_h2[nxt][k*HD2+j] = h2;
                }
            }
        }
        gbar();

        // -------- B: o = tanh(W_cat @ [h2, x] + b_cat) --------
        for (int i = tid; i < KB*HD2; i += NT) ((float*)hs)[i] = __ldcg(&g_h2[nxt][i]);
        __syncthreads();
        for (int j = gwarp; j < HD2; j += NWARP){
            float acc[KB] = {0.f,0.f,0.f,0.f};
            const float4* wr = (const float4*)(Wcat + (size_t)j*(2*HD2));
            #pragma unroll 2
            for (int q = 0; q < 8; q++){
                int m = lane + 32*q;
                float4 w1 = __ldg(&wr[m]);
                float4 w2 = __ldg(&wr[256+m]);
                #pragma unroll
                for (int k = 0; k < KB; k++)
                    acc[k] += dot4(w1, hs[k*256+m]) + dot4(w2, xs[k*256+m]);
            }
            #pragma unroll
            for (int o = 16; o; o >>= 1)
                #pragma unroll
                for (int k = 0; k < KB; k++)
                    acc[k] += __shfl_xor_sync(0xffffffffu, acc[k], o);
            if (lane == 0){
                float bb = __ldg(&bcat[j]);
                #pragma unroll
                for (int k = 0; k < KB; k++)
                    g_o[k*HD2+j] = tanhf(acc[k] + bb);
            }
        }
        gbar();

        // -------- C: logits (4 rows/warp, streaming Wout) + online (max,expsum) --------
        float4* os = smem4;   // [4][256]
        for (int i = tid; i < KB*HD2; i += NT) ((float*)os)[i] = __ldcg(&g_o[i]);
        __syncthreads();
        {
            float mw[KB] = {-FLT_MAX,-FLT_MAX,-FLT_MAX,-FLT_MAX};
            float sw[KB] = {0.f,0.f,0.f,0.f};
            for (int v0 = gwarp*4; v0 < VV; v0 += NWARP*4){
                float acc[4][KB];
                #pragma unroll
                for (int r = 0; r < 4; r++)
                    #pragma unroll
                    for (int k = 0; k < KB; k++) acc[r][k] = 0.f;
                #pragma unroll 2
                for (int q = 0; q < 8; q++){
                    int m = lane + 32*q;
                    float4 o0 = os[0*256+m], o1 = os[1*256+m];
                    float4 o2 = os[2*256+m], o3 = os[3*256+m];
                    #pragma unroll
                    for (int r = 0; r < 4; r++){
                        float4 w = ldcs4((const float4*)(Wout + (size_t)(v0+r)*HD2) + m);
                        acc[r][0] += dot4(w, o0);
                        acc[r][1] += dot4(w, o1);
                        acc[r][2] += dot4(w, o2);
                        acc[r][3] += dot4(w, o3);
                    }
                }
                #pragma unroll
                for (int o = 16; o; o >>= 1)
                    #pragma unroll
                    for (int r = 0; r < 4; r++)
                        #pragma unroll
                        for (int k = 0; k < KB; k++)
                            acc[r][k] += __shfl_xor_sync(0xffffffffu, acc[r][k], o);
                if (lane == 0){
                    #pragma unroll
                    for (int r = 0; r < 4; r++){
                        float bo = __ldg(&bout[v0+r]);
                        #pragma unroll
                        for (int k = 0; k < KB; k++){
                            float l = acc[r][k] + bo;
                            g_logits[(size_t)k*VV + v0 + r] = l;
                            if (l > mw[k]){ sw[k] = sw[k]*expf(mw[k]-l) + 1.f; mw[k] = l; }
                            else          { sw[k] += expf(l - mw[k]); }
                        }
                    }
                }
            }
            if (lane == 0)
                #pragma unroll
                for (int k = 0; k < KB; k++){ sm_m[wid][k] = mw[k]; sm_s[wid][k] = sw[k]; }
            __syncthreads();
            if (tid < KB){
                const int k = tid;
                float m = -FLT_MAX, s = 0.f;
                #pragma unroll
                for (int w = 0; w < 8; w++){
                    float mwv = sm_m[w][k], swv = sm_s[w][k];
                    if (mwv > m){ s = s*expf(m-mwv) + swv; m = mwv; }
                    else        { s += swv*expf(mwv-m); }
                }
                g_pmax[bid*KB+k] = m;
                g_psum[bid*KB+k] = s;
            }
        }
        gbar();

        // -------- E: global (m,S); sc=ftz chain; per-block top-4 --------
        if (wid < KB){
            const int k = wid;
            float mloc = -FLT_MAX;
            for (int i = lane; i < NB; i += 32)
                mloc = fmaxf(mloc, __ldcg(&g_pmax[i*KB+k]));
            #pragma unroll
            for (int o = 16; o; o >>= 1) mloc = fmaxf(mloc, __shfl_xor_sync(0xffffffffu, mloc, o));
            float sloc = 0.f;
            for (int i = lane; i < NB; i += 32){
                float mb = __ldcg(&g_pmax[i*KB+k]);
                float sb = __ldcg(&g_psum[i*KB+k]);
                sloc += sb*expf(mb - mloc);
            }
            #pragma unroll
            for (int o = 16; o; o >>= 1) sloc += __shfl_xor_sync(0xffffffffu, sloc, o);
            if (lane == 0){ s_gmax[k] = mloc; s_S[k] = sloc; }
        }
        __syncthreads();
        {
            float tv[4] = {-FLT_MAX,-FLT_MAX,-FLT_MAX,-FLT_MAX};
            int   ti[4] = {0x7fffffff,0x7fffffff,0x7fffffff,0x7fffffff};
            for (int v = bid*NT + tid; v < VV; v += NB*NT){
                #pragma unroll
                for (int k = 0; k < KB; k++){
                    float l  = __ldcg(&g_logits[(size_t)k*VV+v]);
                    float e  = ftz(expf(l - s_gmax[k]));
                    float pf = ftz(__fdiv_rn(e, s_S[k]));
                    float sc = ftz(__fmul_rn(s_bp[k], pf));
                    ins4(sc, k*VV+v, tv, ti);
                }
            }
            warp_merge4(tv, ti);
            if (lane == 0)
                #pragma unroll
                for (int j = 0; j < 4; j++){ scv[wid*4+j]=tv[j]; sci[wid*4+j]=ti[j]; }
            __syncthreads();
            if (tid == 0){
                float bv[4] = {-FLT_MAX,-FLT_MAX,-FLT_MAX,-FLT_MAX};
                int   bix[4] = {0x7fffffff,0x7fffffff,0x7fffffff,0x7fffffff};
                for (int i = 0; i < 32; i++) ins4(scv[i], sci[i], bv, bix);
                #pragma unroll
                for (int j = 0; j < 4; j++){ g_candv[bid*4+j]=bv[j]; g_candi[bid*4+j]=bix[j]; }
            }
        }
        gbar();
    }

    // =============== final selection + output ===============
    if (wid == 0){
        float tv[4] = {-FLT_MAX,-FLT_MAX,-FLT_MAX,-FLT_MAX};
        int   ti[4] = {0x7fffffff,0x7fffffff,0x7fffffff,0x7fffffff};
        for (int i = lane; i < NB*KB; i += 32)
            ins4(__ldcg(&g_candv[i]), __ldcg(&g_candi[i]), tv, ti);
        warp_merge4(tv, ti);
        if (lane == 0)
            #pragma unroll
            for (int j = 0; j < 4; j++){
                int idx = ti[j];
                s_bi2[j] = idx / VV;
                s_tok[j] = idx - (idx/VV)*VV;
                s_bp[j]  = tv[j];
            }
    }
    __syncthreads();
    if (bid == 0){
        if (tid < KB*(ML+1)){
            int kk = tid/(ML+1), col = tid%(ML+1);
            int val = (col == ML) ? s_tok[kk]
                                  : g_tok[(ML-1)&1][s_bi2[kk]*(ML+1)+col];
            out[tid] = (float)val;
        }
        if (out_size >= KB*(ML+1)+KB && tid < KB)
            out[KB*(ML+1)+tid] = s_bp[tid];
    }
}

// ---------------- host ----------------
static int pick_idx(const int* sz, int n, int want, int occ){
    int c = 0;
    for (int i = 0; i < n; i++)
        if (sz[i] == want){ if (c == occ) return i; c++; }
    return -1;
}

extern "C" void kernel_launch(void* const* d_in, const int* in_sizes, int n_in,
                              void* d_out, int out_size)
{
    int iv   = pick_idx(in_sizes, n_in, TT*DIN, 0);
    int ie   = pick_idx(in_sizes, n_in, VV*HD2, 0);
    int iWf  = pick_idx(in_sizes, n_in, GE*DIN, 0);
    int iHf  = pick_idx(in_sizes, n_in, GE*HH, 0);
    int ibf  = pick_idx(in_sizes, n_in, GE, 0);
    int iWb  = pick_idx(in_sizes, n_in, GE*DIN, 1);
    int ibb  = pick_idx(in_sizes, n_in, GE, 1);
    int idW  = pick_idx(in_sizes, n_in, 4*HD2*HD2, 0);
    int idH  = pick_idx(in_sizes, n_in, 4*HD2*HD2, 1);
    int idb  = pick_idx(in_sizes, n_in, 4*HD2, 0);
    int iWc  = pick_idx(in_sizes, n_in, HD2*2*HD2, 0);
    int ibc  = pick_idx(in_sizes, n_in, HD2, 0);
    int iWo  = pick_idx(in_sizes, n_in, VV*HD2, 1);
    int ibo  = pick_idx(in_sizes, n_in, VV, 0);
    if (iv<0||ie<0||iWf<0||iHf<0||ibf<0||iWb<0||ibb<0||idW<0||idH<0||idb<0||iWc<0||ibc<0||iWo<0||ibo<0){
        iv=0; ie=1; iWf=2; iHf=3; ibf=4; iWb=5; ibb=7; idW=8; idH=9; idb=10; iWc=11; ibc=12; iWo=13; ibo=14;
    }
    beam_kernel<<<NB, NT>>>(
        (const float*)d_in[iv],  (const float*)d_in[ie],
        (const float*)d_in[iWf], (const float*)d_in[iHf], (const float*)d_in[ibf],
        (const float*)d_in[iWb], (const float*)d_in[ibb],
        (const float*)d_in[idW], (const float*)d_in[idH], (const float*)d_in[idb],
        (const float*)d_in[iWc], (const float*)d_in[ibc],
        (const float*)d_in[iWo], (const float*)d_in[ibo],
        (float*)d_out, out_size);
}